// round 14
// baseline (speedup 1.0000x reference)
#include <cuda_runtime.h>

typedef unsigned long long ULL;

#define NB  2
#define SEQ 512
#define HD  256

// Scratch (allocation-free):
//   g_dproj[b][q][d]  = |w_d|*(dec_proj + bm_d)
//   g_eprojT[b][d][e] = |w_d|*enc_proj
__device__ float g_dproj[NB*SEQ*HD];
__device__ float g_eprojT[NB*HD*SEQ];

__device__ __forceinline__ ULL add2(ULL a, ULL b) {
    ULL r; asm("add.rn.f32x2 %0,%1,%2;" : "=l"(r) : "l"(a), "l"(b)); return r;
}
__device__ __forceinline__ ULL fma2(ULL a, ULL b, ULL c) {
    ULL r; asm("fma.rn.f32x2 %0,%1,%2,%3;" : "=l"(r) : "l"(a), "l"(b), "l"(c)); return r;
}
__device__ __forceinline__ float f_lo(ULL a) { return __uint_as_float((unsigned)a); }
__device__ __forceinline__ float f_hi(ULL a) { return __uint_as_float((unsigned)(a >> 32)); }
__device__ __forceinline__ ULL pack2(float lo, float hi) {
    ULL r; asm("mov.b64 %0,{%1,%2};" : "=l"(r) : "f"(lo), "f"(hi)); return r;
}
// packed relu: max(s,0) per 32-bit lane (2 FMNMX; movs are virtual)
__device__ __forceinline__ ULL relu2(ULL s) {
    return pack2(fmaxf(f_lo(s), 0.f), fmaxf(f_hi(s), 0.f));
}

// ---------------------------------------------------------------------------
// Projection kernel: C = A * B^T, k-pair packed, 16x64 tile, 256 thr,
// per-thread 2 rows x 2 cols (4 outputs).  Grid (128,1,4) = 512 CTAs = 4096 w.
// z: 0,1 = dec (b=0,1) -> g_dproj ; 2,3 = enc (b=0,1) -> g_eprojT
// A staged transposed [kpair][row]: the 2 row-values = 1 LDS.128 broadcast.
// ---------------------------------------------------------------------------
__global__ __launch_bounds__(256) void proj_kernel(
    const float* __restrict__ dec, const float* __restrict__ enc,
    const float* __restrict__ Wm,  const float* __restrict__ bm,
    const float* __restrict__ wo)
{
    __shared__ __align__(16) ULL AtP[16*18];   // [kpair][row], stride 18
    __shared__ __align__(16) ULL BsP[16*66];   // [kpair][col], stride 66

    const int tx = threadIdx.x;                // 0..31 (col pair)
    const int ty = threadIdx.y;                // 0..7  (row pair)
    const int t  = ty*32 + tx;
    const int typ = blockIdx.z >> 1;
    const int b   = blockIdx.z & 1;
    const int bx  = blockIdx.x;

    int row0, col0;
    const float *Ap, *Bp;
    float* Cp;
    int lda, ldb, ldc;
    if (typ == 0) {                            // dec: rows=q (32 tiles), cols=d (4 tiles)
        row0 = (bx >> 2) * 16; col0 = (bx & 3) * 64;
        Ap = dec + (size_t)b*SEQ*HD + (size_t)row0*HD;  lda = HD;
        Bp = Wm + HD + (size_t)col0*(2*HD);             ldb = 2*HD;   // Wd[d][k]
        Cp = g_dproj + (size_t)b*SEQ*HD;                ldc = HD;
    } else {                                   // enc: rows=d (16 tiles), cols=e (8 tiles)
        row0 = (bx >> 3) * 16; col0 = (bx & 7) * 64;
        Ap = Wm + (size_t)row0*(2*HD);                  lda = 2*HD;   // We[d][k]
        Bp = enc + (size_t)b*SEQ*HD + (size_t)col0*HD;  ldb = HD;
        Cp = g_eprojT + (size_t)b*HD*SEQ;               ldc = SEQ;
    }

    ULL acc[2][2];
    acc[0][0]=0ULL; acc[0][1]=0ULL; acc[1][0]=0ULL; acc[1][1]=0ULL;

    for (int c = 0; c < 8; c++) {
        __syncthreads();
        if (t < 128) {                         // stage A transposed [kpair][row]
            int ar = t >> 3, akg = t & 7;      // 16 rows x 8 f4-groups
            float4 av = *(const float4*)(Ap + (size_t)ar*lda + c*32 + akg*4);
            *(float2*)&AtP[(2*akg+0)*18 + ar] = make_float2(av.x, av.y);
            *(float2*)&AtP[(2*akg+1)*18 + ar] = make_float2(av.z, av.w);
        }
        #pragma unroll
        for (int r = 0; r < 2; r++) {          // stage B transposed [kpair][col]
            int f4i = t + r*256;
            int bc = f4i >> 3, bkg = f4i & 7;  // 64 cols x 8 f4-groups
            float4 bv = *(const float4*)(Bp + (size_t)bc*ldb + c*32 + bkg*4);
            *(float2*)&BsP[(2*bkg+0)*66 + bc] = make_float2(bv.x, bv.y);
            *(float2*)&BsP[(2*bkg+1)*66 + bc] = make_float2(bv.z, bv.w);
        }
        __syncthreads();
        #pragma unroll
        for (int kk = 0; kk < 16; kk++) {
            ulonglong2 a2 = *(const ulonglong2*)&AtP[kk*18 + 2*ty];  // rows 0,1 (bcast)
            ulonglong2 b2 = *(const ulonglong2*)&BsP[kk*66 + 2*tx];  // cols 0,1
            acc[0][0] = fma2(a2.x, b2.x, acc[0][0]);
            acc[0][1] = fma2(a2.x, b2.y, acc[0][1]);
            acc[1][0] = fma2(a2.y, b2.x, acc[1][0]);
            acc[1][1] = fma2(a2.y, b2.y, acc[1][1]);
        }
    }

    if (typ == 0) {
        const int d0 = col0 + 2*tx;
        const float aw0 = fabsf(wo[d0]), aw1 = fabsf(wo[d0+1]);
        const float m0  = bm[d0],        m1  = bm[d0+1];
        #pragma unroll
        for (int i=0;i<2;i++) {
            int q = row0 + 2*ty + i;
            float sx = f_lo(acc[i][0]) + f_hi(acc[i][0]);
            float sy = f_lo(acc[i][1]) + f_hi(acc[i][1]);
            *(float2*)(Cp + (size_t)q*ldc + d0) =
                make_float2((sx + m0)*aw0, (sy + m1)*aw1);
        }
    } else {
        const int e0 = col0 + 2*tx;
        #pragma unroll
        for (int i=0;i<2;i++) {
            int d = row0 + 2*ty + i;
            float aw = fabsf(wo[d]);
            float sx = f_lo(acc[i][0]) + f_hi(acc[i][0]);
            float sy = f_lo(acc[i][1]) + f_hi(acc[i][1]);
            *(float2*)(Cp + (size_t)d*ldc + e0) = make_float2(sx*aw, sy*aw);
        }
    }
}

// ---------------------------------------------------------------------------
// Main pairwise kernel: 16q x 64e tile, 256 thr, per-thread 2q x 1 e-pair,
// full d=256 per CTA.  Grid (8,32,2) = 512 CTAs = 4096 warps.
// out[b,q,e] = sum_d sgn(w_d)*relu(u+v) + bo          (u,v scaled by |w|)
// U staged transposed + pair-duplicated: Du[hh][2q+p] (stride 36) -> the 2
// q-values of a thread are 4 consecutive floats = 1 broadcast LDS.128.
// Staging split: threads 0-127 stage U, threads 128-255 stage V.
// ---------------------------------------------------------------------------
__global__ __launch_bounds__(256) void attn_kernel(
    const float* __restrict__ wo, const float* __restrict__ bo,
    float* __restrict__ out)
{
    __shared__ __align__(16) float Du[32*36];   // [hh][2q-dup], stride 36
    __shared__ __align__(16) float Es[32*68];   // [hh][e], stride 68
    __shared__ __align__(16) float Sg[512];     // sgn(w) duplicated pairs

    const int tx = threadIdx.x;                 // 0..31 (e-pair)
    const int ty = threadIdx.y;                 // 0..7  (q-pair group)
    const int t  = ty*32 + tx;
    const int et = blockIdx.x, qt = blockIdx.y, b = blockIdx.z;

    const float* U = g_dproj  + (size_t)b*SEQ*HD + (size_t)qt*16*HD;
    const float* V = g_eprojT + (size_t)b*HD*SEQ + et*64;

    {   // Sg[2d] = Sg[2d+1] = sgn(w_d)
        float w = wo[t];
        float sg = (w > 0.f) ? 1.f : ((w < 0.f) ? -1.f : 0.f);
        Sg[2*t] = sg; Sg[2*t+1] = sg;
    }

    ULL acc[2] = {0ULL, 0ULL};

    for (int c = 0; c < 8; c++) {
        __syncthreads();
        if (t < 128) {                          // stage U transposed + pair-dup
            int uq = t >> 3, uhg = t & 7;       // 16 q x 8 f4-groups
            float4 av = *(const float4*)(U + (size_t)uq*HD + c*32 + uhg*4);
            *(float2*)&Du[(4*uhg+0)*36 + 2*uq] = make_float2(av.x, av.x);
            *(float2*)&Du[(4*uhg+1)*36 + 2*uq] = make_float2(av.y, av.y);
            *(float2*)&Du[(4*uhg+2)*36 + 2*uq] = make_float2(av.z, av.z);
            *(float2*)&Du[(4*uhg+3)*36 + 2*uq] = make_float2(av.w, av.w);
        } else {                                // stage V
            int tv = t - 128;
            int veg = tv & 15, vh0 = tv >> 4;   // 16 f4-cols x 8 row-starts
            #pragma unroll
            for (int r = 0; r < 4; r++) {
                int h = vh0 + r*8;
                *(float4*)&Es[h*68 + veg*4] =
                    *(const float4*)(V + (size_t)(c*32 + h)*SEQ + veg*4);
            }
        }
        __syncthreads();

        #pragma unroll 8
        for (int hh = 0; hh < 32; hh++) {
            ULL sg2 = *(const ULL*)&Sg[(c*32 + hh)*2];
            ULL v2  = *(const ULL*)&Es[hh*68 + 2*tx];
            ulonglong2 u2 = *(const ulonglong2*)&Du[hh*36 + 4*ty];   // q0,q1 (bcast)
            acc[0] = fma2(relu2(add2(u2.x, v2)), sg2, acc[0]);
            acc[1] = fma2(relu2(add2(u2.y, v2)), sg2, acc[1]);
        }
    }

    const float bov = bo[0];
    const int q0 = qt*16 + 2*ty;
    const int e0 = et*64 + 2*tx;
    float* O = out + ((size_t)b*SEQ + q0)*SEQ + e0;
    #pragma unroll
    for (int i=0;i<2;i++) {
        *(float2*)(O + (size_t)i*SEQ) =
            make_float2(f_lo(acc[i]) + bov, f_hi(acc[i]) + bov);
    }
}

extern "C" void kernel_launch(void* const* d_in, const int* in_sizes, int n_in,
                              void* d_out, int out_size)
{
    const float* dec = (const float*)d_in[0];
    const float* enc = (const float*)d_in[1];
    const float* Wm  = (const float*)d_in[2];
    const float* bm  = (const float*)d_in[3];
    const float* wo  = (const float*)d_in[4];
    const float* bo  = (const float*)d_in[5];
    float* out = (float*)d_out;

    proj_kernel<<<dim3(128,1,4), dim3(32,8)>>>(dec, enc, Wm, bm, wo);
    attn_kernel<<<dim3(8,32,2), dim3(32,8)>>>(wo, bo, out);
}

// round 16
// speedup vs baseline: 1.3827x; 1.3827x over previous
#include <cuda_runtime.h>

typedef unsigned long long ULL;

#define NB  2
#define SEQ 512
#define HD  256

// Scratch (allocation-free):
//   g_dproj[b][q][d]  = |w_d|*(dec_proj + bm_d)
//   g_eprojT[b][d][e] = |w_d|*enc_proj
__device__ float g_dproj[NB*SEQ*HD];
__device__ float g_eprojT[NB*HD*SEQ];

__device__ __forceinline__ ULL add2(ULL a, ULL b) {
    ULL r; asm("add.rn.f32x2 %0,%1,%2;" : "=l"(r) : "l"(a), "l"(b)); return r;
}
__device__ __forceinline__ ULL fma2(ULL a, ULL b, ULL c) {
    ULL r; asm("fma.rn.f32x2 %0,%1,%2,%3;" : "=l"(r) : "l"(a), "l"(b), "l"(c)); return r;
}
__device__ __forceinline__ float f_lo(ULL a) { return __uint_as_float((unsigned)a); }
__device__ __forceinline__ float f_hi(ULL a) { return __uint_as_float((unsigned)(a >> 32)); }
__device__ __forceinline__ ULL pack2(float lo, float hi) {
    ULL r; asm("mov.b64 %0,{%1,%2};" : "=l"(r) : "f"(lo), "f"(hi)); return r;
}
// packed relu: max(s,0) per 32-bit lane (2 FMNMX; movs are virtual)
__device__ __forceinline__ ULL relu2(ULL s) {
    return pack2(fmaxf(f_lo(s), 0.f), fmaxf(f_hi(s), 0.f));
}

// ---------------------------------------------------------------------------
// Projection kernel: C = A * B^T, k-pair packed, 32x64 tile, 256 thr,
// per-thread 4 rows x 2 cols.  Grid (64,1,4).  (R13-proven kernel.)
// z: 0,1 = dec (b=0,1) -> g_dproj ; 2,3 = enc (b=0,1) -> g_eprojT
// ---------------------------------------------------------------------------
__global__ __launch_bounds__(256) void proj_kernel(
    const float* __restrict__ dec, const float* __restrict__ enc,
    const float* __restrict__ Wm,  const float* __restrict__ bm,
    const float* __restrict__ wo)
{
    __shared__ __align__(16) ULL AsP[32*17];   // [row][kpair], stride 17
    __shared__ __align__(16) ULL BsP[16*66];   // [kpair][col], stride 66

    const int tx = threadIdx.x;                // 0..31
    const int ty = threadIdx.y;                // 0..7
    const int t  = ty*32 + tx;
    const int typ = blockIdx.z >> 1;
    const int b   = blockIdx.z & 1;
    const int bx  = blockIdx.x;

    int row0, col0;
    const float *Ap, *Bp;
    float* Cp;
    int lda, ldb, ldc;
    if (typ == 0) {                            // dec: rows=q (16 tiles), cols=d (4 tiles)
        row0 = (bx >> 2) * 32; col0 = (bx & 3) * 64;
        Ap = dec + (size_t)b*SEQ*HD + (size_t)row0*HD;  lda = HD;
        Bp = Wm + HD + (size_t)col0*(2*HD);             ldb = 2*HD;   // Wd[d][k]
        Cp = g_dproj + (size_t)b*SEQ*HD;                ldc = HD;
    } else {                                   // enc: rows=d (8 tiles), cols=e (8 tiles)
        row0 = (bx >> 3) * 32; col0 = (bx & 7) * 64;
        Ap = Wm + (size_t)row0*(2*HD);                  lda = 2*HD;   // We[d][k]
        Bp = enc + (size_t)b*SEQ*HD + (size_t)col0*HD;  ldb = HD;
        Cp = g_eprojT + (size_t)b*HD*SEQ;               ldc = SEQ;
    }

    ULL acc[4][2];
    #pragma unroll
    for (int i=0;i<4;i++){ acc[i][0]=0ULL; acc[i][1]=0ULL; }

    const int ar = t >> 3, akg = t & 7;        // A: 32 rows x 8 f4-groups

    for (int c = 0; c < 8; c++) {
        __syncthreads();
        {   // stage A (k-pairs, natural order)
            float4 av = *(const float4*)(Ap + (size_t)ar*lda + c*32 + akg*4);
            float2* pa = (float2*)&AsP[ar*17 + akg*2];
            pa[0] = make_float2(av.x, av.y);
            pa[1] = make_float2(av.z, av.w);
        }
        #pragma unroll
        for (int r = 0; r < 2; r++) {          // stage B transposed to [kpair][col]
            int f4i = t + r*256;
            int bc = f4i >> 3, bkg = f4i & 7;
            float4 bv = *(const float4*)(Bp + (size_t)bc*ldb + c*32 + bkg*4);
            *(float2*)&BsP[(bkg*2+0)*66 + bc] = make_float2(bv.x, bv.y);
            *(float2*)&BsP[(bkg*2+1)*66 + bc] = make_float2(bv.z, bv.w);
        }
        __syncthreads();
        #pragma unroll
        for (int kk = 0; kk < 16; kk++) {
            ULL a2[4];
            #pragma unroll
            for (int i=0;i<4;i++) a2[i] = AsP[(4*ty+i)*17 + kk];
            ulonglong2 b2 = *(const ulonglong2*)&BsP[kk*66 + 2*tx];  // LDS.128
            #pragma unroll
            for (int i=0;i<4;i++){
                acc[i][0] = fma2(a2[i], b2.x, acc[i][0]);
                acc[i][1] = fma2(a2[i], b2.y, acc[i][1]);
            }
        }
    }

    if (typ == 0) {
        const int d0 = col0 + 2*tx;
        const float aw0 = fabsf(wo[d0]), aw1 = fabsf(wo[d0+1]);
        const float m0  = bm[d0],        m1  = bm[d0+1];
        #pragma unroll
        for (int i=0;i<4;i++) {
            int q = row0 + 4*ty + i;
            float sx = f_lo(acc[i][0]) + f_hi(acc[i][0]);
            float sy = f_lo(acc[i][1]) + f_hi(acc[i][1]);
            *(float2*)(Cp + (size_t)q*ldc + d0) =
                make_float2((sx + m0)*aw0, (sy + m1)*aw1);
        }
    } else {
        const int e0 = col0 + 2*tx;
        #pragma unroll
        for (int i=0;i<4;i++) {
            int d = row0 + 4*ty + i;
            float aw = fabsf(wo[d]);
            float sx = f_lo(acc[i][0]) + f_hi(acc[i][0]);
            float sy = f_lo(acc[i][1]) + f_hi(acc[i][1]);
            *(float2*)(Cp + (size_t)d*ldc + e0) = make_float2(sx*aw, sy*aw);
        }
    }
}

// ---------------------------------------------------------------------------
// Main pairwise kernel: 16q x 64e tile, 128 thr (FLAT), warp owns 4q x 64e,
// per-thread 4q x 1 e-pair.  Grid (8,32,2) = 512 CTAs = 2048 warps.
// out[b,q,e] = sum_d sgn(w_d)*relu(u+v) + bo          (u,v scaled by |w|)
// V: direct LDG with 8-deep register prefetch ring (no smem, no V staging).
// U: double-buffered smem chunks (32 d), register-prefetched LDG, ONE sync
//    per chunk.  U stored transposed + pair-duplicated: Du[hh][2q+p] so a
//    warp's 4 q-values = 2 broadcast LDS.128.
// ---------------------------------------------------------------------------
__global__ __launch_bounds__(128) void attn_kernel(
    const float* __restrict__ wo, const float* __restrict__ bo,
    float* __restrict__ out)
{
    __shared__ __align__(16) float Du[2][32*36];  // [buf][hh][2q-dup], stride 36
    __shared__ __align__(16) float Sg[512];       // sgn(w) duplicated pairs

    const int t  = threadIdx.x;                 // 0..127 (flat launch!)
    const int tx = t & 31;                      // e-pair lane
    const int wy = t >> 5;                      // 0..3, q-group (4q per warp)
    const int et = blockIdx.x, qt = blockIdx.y, b = blockIdx.z;

    const float* U    = g_dproj  + (size_t)b*SEQ*HD + (size_t)qt*16*HD;
    const float* Vrow = g_eprojT + (size_t)b*HD*SEQ + et*64 + 2*tx;

    #pragma unroll
    for (int k = t; k < HD; k += 128) {         // Sg[2d]=Sg[2d+1]=sgn(w_d)
        float w = wo[k];
        float sg = (w > 0.f) ? 1.f : ((w < 0.f) ? -1.f : 0.f);
        Sg[2*k] = sg; Sg[2*k+1] = sg;
    }

    const int uq = t >> 3, uhg = t & 7;         // U staging: 16 q x 8 f4-groups

    // V prefetch ring: d = 0..7
    ULL vbuf[8];
    #pragma unroll
    for (int i = 0; i < 8; i++)
        vbuf[i] = *(const ULL*)(Vrow + (size_t)i*SEQ);

    // U chunk 0 into registers
    float4 ucur = *(const float4*)(U + (size_t)uq*HD + uhg*4);

    ULL acc[4] = {0ULL,0ULL,0ULL,0ULL};

    for (int c = 0; c < 8; c++) {
        float* D = Du[c & 1];
        // stage current U chunk (transposed + pair-duplicated)
        *(float2*)&D[(4*uhg+0)*36 + 2*uq] = make_float2(ucur.x, ucur.x);
        *(float2*)&D[(4*uhg+1)*36 + 2*uq] = make_float2(ucur.y, ucur.y);
        *(float2*)&D[(4*uhg+2)*36 + 2*uq] = make_float2(ucur.z, ucur.z);
        *(float2*)&D[(4*uhg+3)*36 + 2*uq] = make_float2(ucur.w, ucur.w);
        __syncthreads();
        if (c < 7)                              // prefetch next U chunk
            ucur = *(const float4*)(U + (size_t)uq*HD + (c+1)*32 + uhg*4);

        #pragma unroll
        for (int i = 0; i < 32; i++) {
            const int d = c*32 + i;
            ULL v2 = vbuf[i & 7];
            const int dp = (d + 8) & (HD - 1);  // safe wrap on last chunk
            vbuf[i & 7] = *(const ULL*)(Vrow + (size_t)dp*SEQ);
            ULL sg2 = *(const ULL*)&Sg[2*d];
            ulonglong2 u01 = *(const ulonglong2*)&D[i*36 + 8*wy];      // q0,q1
            ulonglong2 u23 = *(const ulonglong2*)&D[i*36 + 8*wy + 4];  // q2,q3
            acc[0] = fma2(relu2(add2(u01.x, v2)), sg2, acc[0]);
            acc[1] = fma2(relu2(add2(u01.y, v2)), sg2, acc[1]);
            acc[2] = fma2(relu2(add2(u23.x, v2)), sg2, acc[2]);
            acc[3] = fma2(relu2(add2(u23.y, v2)), sg2, acc[3]);
        }
    }

    const float bov = bo[0];
    const int q0 = qt*16 + 4*wy;
    float* O = out + ((size_t)b*SEQ + q0)*SEQ + et*64 + 2*tx;
    #pragma unroll
    for (int i=0;i<4;i++) {
        *(float2*)(O + (size_t)i*SEQ) =
            make_float2(f_lo(acc[i]) + bov, f_hi(acc[i]) + bov);
    }
}

extern "C" void kernel_launch(void* const* d_in, const int* in_sizes, int n_in,
                              void* d_out, int out_size)
{
    const float* dec = (const float*)d_in[0];
    const float* enc = (const float*)d_in[1];
    const float* Wm  = (const float*)d_in[2];
    const float* bm  = (const float*)d_in[3];
    const float* wo  = (const float*)d_in[4];
    const float* bo  = (const float*)d_in[5];
    float* out = (float*)d_out;

    proj_kernel<<<dim3(64,1,4), dim3(32,8)>>>(dec, enc, Wm, bm, wo);
    attn_kernel<<<dim3(8,32,2), dim3(128,1,1)>>>(wo, bo, out);
}